// round 17
// baseline (speedup 1.0000x reference)
#include <cuda_runtime.h>
#include <cstdint>

#define IN_F   4096
#define OUT_F  4096
#define NTHREADS 256
#define NBLOCKS  592    // 148 SMs * 4 CTAs, persistent grid-stride over rows

__global__ __launch_bounds__(NTHREADS, 4)
void unary_linear_kernel(
    const float* __restrict__ x,          // [1, IN_F]
    const float* __restrict__ buf_wght,   // [OUT_F, IN_F]
    const float* __restrict__ buf_bias,   // [OUT_F]
    const float* __restrict__ acc,        // [1, OUT_F]
    const float* __restrict__ acc_bound,  // [1]
    const int*   __restrict__ rng_wght_idx,     // [OUT_F, IN_F] int32
    const int*   __restrict__ rng_bias_idx,     // [OUT_F]
    const int*   __restrict__ rng_wght_idx_inv, // [OUT_F, IN_F]
    float*       __restrict__ out)        // [1, OUT_F]
{
    __shared__ float s_red[2][NTHREADS / 32];

    const int tid  = threadIdx.x;
    const int lane = tid & 31;
    const int wid  = tid >> 5;

    // pack this thread's 16 x-bits once per CTA (x is 16 KB, L2-hot)
    const float4* xv4 = (const float4*)x;
    uint32_t xb = 0;
    #pragma unroll
    for (int q = 0; q < 4; q++) {
        float4 xq = __ldg(xv4 + tid + q * NTHREADS);
        xb |= (uint32_t)(xq.x > 0.5f) << (4 * q + 0);
        xb |= (uint32_t)(xq.y > 0.5f) << (4 * q + 1);
        xb |= (uint32_t)(xq.z > 0.5f) << (4 * q + 2);
        xb |= (uint32_t)(xq.w > 0.5f) << (4 * q + 3);
    }
    const float bound = __ldg(acc_bound);

    float4 w[4];
    int4   ki[4], kv[4];

    // ---- prefetch first row: 12 consecutive LDG.128 ----
    int j = blockIdx.x;
    {
        const size_t row = (size_t)j * IN_F;
        const float4* wrow = (const float4*)(buf_wght        + row);
        const int4*   iwr  = (const int4*)  (rng_wght_idx     + row);
        const int4*   ivr  = (const int4*)  (rng_wght_idx_inv + row);
        #pragma unroll
        for (int it = 0; it < 4; it++) w[it]  = __ldcs(wrow + tid + it * NTHREADS);
        #pragma unroll
        for (int it = 0; it < 4; it++) ki[it] = __ldcs(iwr  + tid + it * NTHREADS);
        #pragma unroll
        for (int it = 0; it < 4; it++) kv[it] = __ldcs(ivr  + tid + it * NTHREADS);
    }

    int buf = 0;
    while (true) {
        // ---- compute current row from registers (frees them as consumed) ----
        int sum = 0;
        #pragma unroll
        for (int it = 0; it < 4; it++) {
            uint32_t nib = xb >> (4 * it);
            // rng[k % 256] == (float)(__brev(k) >> 24)  (8-bit van der Corput)
            {
                bool b = (nib & 1u) != 0;
                uint32_t r = b ? (__brev((uint32_t)ki[it].x) >> 24) : (__brev((uint32_t)kv[it].x) >> 24);
                sum += ((w[it].x >= (float)r) == b);
            }
            {
                bool b = (nib & 2u) != 0;
                uint32_t r = b ? (__brev((uint32_t)ki[it].y) >> 24) : (__brev((uint32_t)kv[it].y) >> 24);
                sum += ((w[it].y >= (float)r) == b);
            }
            {
                bool b = (nib & 4u) != 0;
                uint32_t r = b ? (__brev((uint32_t)ki[it].z) >> 24) : (__brev((uint32_t)kv[it].z) >> 24);
                sum += ((w[it].z >= (float)r) == b);
            }
            {
                bool b = (nib & 8u) != 0;
                uint32_t r = b ? (__brev((uint32_t)ki[it].w) >> 24) : (__brev((uint32_t)kv[it].w) >> 24);
                sum += ((w[it].w >= (float)r) == b);
            }
        }

        // ---- issue next row's loads BEFORE the reduction barrier ----
        const int jn = j + NBLOCKS;
        if (jn < OUT_F) {
            const size_t row = (size_t)jn * IN_F;
            const float4* wrow = (const float4*)(buf_wght        + row);
            const int4*   iwr  = (const int4*)  (rng_wght_idx     + row);
            const int4*   ivr  = (const int4*)  (rng_wght_idx_inv + row);
            #pragma unroll
            for (int it = 0; it < 4; it++) w[it]  = __ldcs(wrow + tid + it * NTHREADS);
            #pragma unroll
            for (int it = 0; it < 4; it++) ki[it] = __ldcs(iwr  + tid + it * NTHREADS);
            #pragma unroll
            for (int it = 0; it < 4; it++) kv[it] = __ldcs(ivr  + tid + it * NTHREADS);
        }

        // ---- reduce + epilogue for row j (overlaps with in-flight loads) ----
        sum = __reduce_add_sync(0xFFFFFFFFu, sum);
        if (lane == 0) s_red[buf][wid] = (float)sum;
        __syncthreads();

        if (tid == 0) {
            float total = 0.0f;
            #pragma unroll
            for (int w8 = 0; w8 < NTHREADS / 32; w8++) total += s_red[buf][w8];
            uint32_t kb = __brev((uint32_t)__ldg(rng_bias_idx + j)) >> 24;
            float b_bit = (__ldg(buf_bias + j) >= (float)kb) ? 1.0f : 0.0f;
            float acc_new = __ldg(acc + j) + total + b_bit;
            out[j] = (acc_new >= bound) ? 1.0f : 0.0f;
        }

        if (jn >= OUT_F) break;
        j = jn;
        buf ^= 1;
    }
}

extern "C" void kernel_launch(void* const* d_in, const int* in_sizes, int n_in,
                              void* d_out, int out_size)
{
    const float* x            = (const float*)d_in[0];
    const float* buf_wght     = (const float*)d_in[1];
    const float* buf_bias     = (const float*)d_in[2];
    const float* acc          = (const float*)d_in[4];
    const float* acc_bound    = (const float*)d_in[5];
    const int*   rng_wght_idx     = (const int*)d_in[6];
    const int*   rng_bias_idx     = (const int*)d_in[7];
    const int*   rng_wght_idx_inv = (const int*)d_in[8];
    float* out = (float*)d_out;

    unary_linear_kernel<<<NBLOCKS, NTHREADS>>>(
        x, buf_wght, buf_bias, acc, acc_bound,
        rng_wght_idx, rng_bias_idx, rng_wght_idx_inv, out);
}